// round 10
// baseline (speedup 1.0000x reference)
#include <cuda_runtime.h>

// ---------------- problem constants (fixed by reference) ----------------
#define NB    16          // batch lines
#define CC    512         // channels
#define WW    4096        // max width
#define FD    512         // final dim
#define MW    4           // mask width
#define NM    256         // num masks
#define NNEG  10          // num negatives
#define M1    (NM * MW)         // 1024 masked rows
#define M2    (NNEG * NM * MW)  // 10240 negative rows
#define MTOT  (M1 + M2)         // 11264 GEMM rows
#define OUT_REGION0 (NB * CC * WW)   // 33,554,432 floats: the padded (N,C,1,W) output

// 23 MB scratch: gathered packed rows [MTOT, CC], row-major (K-contiguous)
__device__ float g_Ag[(size_t)MTOT * CC];

// ---------------------------------------------------------------------------
// K1: out[n,c,0,w] = inputs[n,c,0,w] if w < seq_len[n] else 0   (float4 wide)
// ---------------------------------------------------------------------------
__global__ void k_copy(const float* __restrict__ in,
                       const int*   __restrict__ seq_len,
                       float*       __restrict__ out) {
    int idx = blockIdx.x * blockDim.x + threadIdx.x;   // over NB*CC*WW/4 = 8,388,608
    int w   = (idx & (WW / 4 - 1)) << 2;               // w4 * 4
    int nc  = idx >> 10;                               // n*CC + c
    int n   = nc >> 9;                                 // / CC
    int len = __ldg(&seq_len[n]);
    float4 v = ((const float4*)in)[idx];
    if (w + 3 >= len) {                                // rare boundary / padded tail
        if (w + 0 >= len) v.x = 0.f;
        if (w + 1 >= len) v.y = 0.f;
        if (w + 2 >= len) v.z = 0.f;
        v.w = 0.f;
    }
    ((float4*)out)[idx] = v;
}

// ---------------------------------------------------------------------------
// K2: overwrite the 1024 masked positions with tiled mask_emb rows.
// block i in [0,1024): flat f = pack_idx[masked_idx[i]]; out[n, c, w] = mask_emb[i%4, c]
// ---------------------------------------------------------------------------
__global__ void k_mask(const int*   __restrict__ pack_idx,
                       const int*   __restrict__ masked_idx,
                       const float* __restrict__ mask_emb,
                       float*       __restrict__ out) {
    int i = blockIdx.x;          // 0..M1-1
    int c = threadIdx.x;         // 0..CC-1
    int f = __ldg(&pack_idx[__ldg(&masked_idx[i])]);
    int n = f >> 12;             // f / WW
    int w = f & (WW - 1);
    out[(n * CC + c) * WW + w] = __ldg(&mask_emb[(i & (MW - 1)) * CC + c]);
}

// ---------------------------------------------------------------------------
// K3: gather the 11264 packed rows (pre-mask values!) into contiguous g_Ag.
// Row r < M1 -> masked_idx[r]; else neg_idx[r - M1].
// Reads are stride-16KB scattered (inherent); writes fully coalesced.
// ---------------------------------------------------------------------------
__global__ void k_gather(const float* __restrict__ in,
                         const int*   __restrict__ pack_idx,
                         const int*   __restrict__ masked_idx,
                         const int*   __restrict__ neg_idx) {
    int r = blockIdx.x;          // 0..MTOT-1
    int c = threadIdx.x;         // 0..CC-1
    int p = (r < M1) ? __ldg(&masked_idx[r]) : __ldg(&neg_idx[r - M1]);
    int f = __ldg(&pack_idx[p]);
    int n = f >> 12;
    int w = f & (WW - 1);
    g_Ag[r * CC + c] = __ldg(&in[(n * CC + c) * WW + w]);
}

// ---------------------------------------------------------------------------
// K4: D[MTOT, FD] = g_Ag[MTOT, CC] @ Wq[FD, CC]^T + bq   (fp32 SGEMM)
// Both operands K-major. 128x128 block tile, BK=8, 256 threads, 8x8/thread,
// register prefetch of next global tile under the compute of the current one.
// unmasked rows [0,1024) and negatives rows [1024,11264) are contiguous in
// d_out, so D is simply d_out + OUT_REGION0.
// ---------------------------------------------------------------------------
#define BM 128
#define BN 128
#define BK 8

__global__ __launch_bounds__(256, 2)
void k_gemm(const float* __restrict__ B,      // Wq [FD, CC]
            const float* __restrict__ bias,   // bq [FD]
            float*       __restrict__ D) {
    __shared__ float As[BK][BM];
    __shared__ float Bs[BK][BN];

    const int bn  = blockIdx.x;          // 0..FD/BN-1
    const int bm  = blockIdx.y;          // 0..MTOT/BM-1
    const int tid = threadIdx.x;         // 0..255
    const int tx  = tid & 15;            // 16 x 16 thread grid
    const int ty  = tid >> 4;

    // global -> smem loader mapping: 256 threads cover 128 rows x 8 k (float4 in k)
    const int lrow = tid >> 1;
    const int lk   = (tid & 1) << 2;

    const float* Aptr = g_Ag + (bm * BM + lrow) * CC + lk;
    const float* Bptr = B    + (bn * BN + lrow) * CC + lk;

    float acc[8][8];
#pragma unroll
    for (int i = 0; i < 8; i++)
#pragma unroll
        for (int j = 0; j < 8; j++) acc[i][j] = 0.f;

    float4 av = *(const float4*)(Aptr);
    float4 bv = *(const float4*)(Bptr);

#pragma unroll 1
    for (int k0 = 0; k0 < CC; k0 += BK) {
        // stage current tile (transposed to [k][row/col])
        As[lk + 0][lrow] = av.x; As[lk + 1][lrow] = av.y;
        As[lk + 2][lrow] = av.z; As[lk + 3][lrow] = av.w;
        Bs[lk + 0][lrow] = bv.x; Bs[lk + 1][lrow] = bv.y;
        Bs[lk + 2][lrow] = bv.z; Bs[lk + 3][lrow] = bv.w;
        __syncthreads();

        // prefetch next tile into registers (hidden under FFMA below)
        if (k0 + BK < CC) {
            av = *(const float4*)(Aptr + k0 + BK);
            bv = *(const float4*)(Bptr + k0 + BK);
        }

#pragma unroll
        for (int k = 0; k < BK; k++) {
            float4 a0 = *(const float4*)&As[k][ty * 8];
            float4 a1 = *(const float4*)&As[k][ty * 8 + 4];
            float4 b0 = *(const float4*)&Bs[k][tx * 8];
            float4 b1 = *(const float4*)&Bs[k][tx * 8 + 4];
            float a[8] = {a0.x, a0.y, a0.z, a0.w, a1.x, a1.y, a1.z, a1.w};
            float b[8] = {b0.x, b0.y, b0.z, b0.w, b1.x, b1.y, b1.z, b1.w};
#pragma unroll
            for (int i = 0; i < 8; i++)
#pragma unroll
                for (int j = 0; j < 8; j++)
                    acc[i][j] += a[i] * b[j];
        }
        __syncthreads();
    }

    // epilogue: += bias, store
    const int colbase = bn * BN + tx * 8;
    float bb[8];
#pragma unroll
    for (int j = 0; j < 8; j++) bb[j] = __ldg(&bias[colbase + j]);

#pragma unroll
    for (int i = 0; i < 8; i++) {
        int r = bm * BM + ty * 8 + i;
        float* drow = D + (size_t)r * FD + colbase;
        float4 v0, v1;
        v0.x = acc[i][0] + bb[0]; v0.y = acc[i][1] + bb[1];
        v0.z = acc[i][2] + bb[2]; v0.w = acc[i][3] + bb[3];
        v1.x = acc[i][4] + bb[4]; v1.y = acc[i][5] + bb[5];
        v1.z = acc[i][6] + bb[6]; v1.w = acc[i][7] + bb[7];
        *(float4*)(drow + 0) = v0;
        *(float4*)(drow + 4) = v1;
    }
}

// ---------------------------------------------------------------------------
// launch
// ---------------------------------------------------------------------------
extern "C" void kernel_launch(void* const* d_in, const int* in_sizes, int n_in,
                              void* d_out, int out_size) {
    (void)in_sizes; (void)n_in; (void)out_size;
    const float* inputs     = (const float*)d_in[0];
    const int*   seq_len    = (const int*)  d_in[1];
    const int*   pack_idx   = (const int*)  d_in[2];
    const int*   masked_idx = (const int*)  d_in[3];
    const int*   neg_idx    = (const int*)  d_in[4];
    const float* mask_emb   = (const float*)d_in[5];
    const float* Wq         = (const float*)d_in[6];
    const float* bq         = (const float*)d_in[7];
    float* out = (float*)d_out;

    // region 0: padded masked copy (then mask-embedding scatter)
    k_copy<<<(NB * CC * WW / 4) / 256, 256>>>(inputs, seq_len, out);
    k_mask<<<M1, CC>>>(pack_idx, masked_idx, mask_emb, out);

    // regions 1+2: gather pre-mask rows, then one fused GEMM + bias
    k_gather<<<MTOT, CC>>>(inputs, pack_idx, masked_idx, neg_idx);
    dim3 grid(FD / BN, MTOT / BM);   // (4, 88)
    k_gemm<<<grid, 256>>>(Wq, bq, out + OUT_REGION0);
}

// round 11
// speedup vs baseline: 1.3572x; 1.3572x over previous
#include <cuda_runtime.h>
#include <cstdint>

// ---------------- problem constants (fixed by reference) ----------------
#define NB    16          // batch lines
#define CC    512         // channels (= GEMM K)
#define WW    4096        // max width
#define FD    512         // final dim (= GEMM N)
#define MW    4           // mask width
#define NM    256         // num masks
#define NNEG  10          // num negatives
#define M1    (NM * MW)         // 1024 masked rows
#define M2    (NNEG * NM * MW)  // 10240 negative rows
#define MTOT  (M1 + M2)         // 11264 GEMM rows
#define OUT_REGION0 (NB * CC * WW)   // 33,554,432 floats

// 23 MB scratch: gathered packed rows [MTOT, CC], row-major (K-contiguous)
__device__ float g_Ag[(size_t)MTOT * CC];

// ---------------------------------------------------------------------------
// K1: out[n,c,0,w] = inputs[n,c,0,w] if w < seq_len[n] else 0   (float4 wide)
// ---------------------------------------------------------------------------
__global__ void k_copy(const float* __restrict__ in,
                       const int*   __restrict__ seq_len,
                       float*       __restrict__ out) {
    int idx = blockIdx.x * blockDim.x + threadIdx.x;   // NB*CC*WW/4 lanes
    int w   = (idx & (WW / 4 - 1)) << 2;
    int nc  = idx >> 10;
    int n   = nc >> 9;
    int len = __ldg(&seq_len[n]);
    float4 v = ((const float4*)in)[idx];
    if (w + 3 >= len) {
        if (w + 0 >= len) v.x = 0.f;
        if (w + 1 >= len) v.y = 0.f;
        if (w + 2 >= len) v.z = 0.f;
        v.w = 0.f;
    }
    ((float4*)out)[idx] = v;
}

// ---------------------------------------------------------------------------
// K2: overwrite the 1024 masked positions with tiled mask_emb rows.
// ---------------------------------------------------------------------------
__global__ void k_mask(const int*   __restrict__ pack_idx,
                       const int*   __restrict__ masked_idx,
                       const float* __restrict__ mask_emb,
                       float*       __restrict__ out) {
    int i = blockIdx.x;          // 0..M1-1
    int c = threadIdx.x;         // 0..CC-1
    int f = __ldg(&pack_idx[__ldg(&masked_idx[i])]);
    int n = f >> 12;
    int w = f & (WW - 1);
    out[(n * CC + c) * WW + w] = __ldg(&mask_emb[(i & (MW - 1)) * CC + c]);
}

// ---------------------------------------------------------------------------
// K3: gather the 11264 packed rows (pre-mask values) into contiguous g_Ag.
// ---------------------------------------------------------------------------
__global__ void k_gather(const float* __restrict__ in,
                         const int*   __restrict__ pack_idx,
                         const int*   __restrict__ masked_idx,
                         const int*   __restrict__ neg_idx) {
    int r = blockIdx.x;          // 0..MTOT-1
    int c = threadIdx.x;         // 0..CC-1
    int p = (r < M1) ? __ldg(&masked_idx[r]) : __ldg(&neg_idx[r - M1]);
    int f = __ldg(&pack_idx[p]);
    int n = f >> 12;
    int w = f & (WW - 1);
    g_Ag[r * CC + c] = __ldg(&in[(n * CC + c) * WW + w]);
}

// ---------------------------------------------------------------------------
// K4: D[MTOT, FD] = g_Ag @ Wq^T + bq   via tensor cores (tf32 mma.sync)
//
//   Block tile 64(M) x 128(N), BK=16, 256 threads = 8 warps (2 M x 4 N),
//   warp tile 32x32 -> 2x4 m16n8k8 fragments, fp32 accumulate.
//   Double-buffered smem fed by cp.async; smem rows padded 16->20 floats so
//   fragment LDS is conflict-free (bank = (20g + t) mod 32, all-distinct).
// ---------------------------------------------------------------------------
#define GBM 64
#define GBN 128
#define GBK 16
#define SPAD 20
#define NSTAGE (CC / GBK)     // 32

__device__ __forceinline__ void cpasync16(void* smem_dst, const void* gsrc) {
    unsigned s = (unsigned)__cvta_generic_to_shared(smem_dst);
    asm volatile("cp.async.cg.shared.global [%0], [%1], 16;\n" :: "r"(s), "l"(gsrc));
}
__device__ __forceinline__ void cpasync_commit() {
    asm volatile("cp.async.commit_group;\n" ::: "memory");
}
template<int N> __device__ __forceinline__ void cpasync_wait() {
    asm volatile("cp.async.wait_group %0;\n" :: "n"(N) : "memory");
}
__device__ __forceinline__ uint32_t f2tf(float f) {
    uint32_t r;
    asm("cvt.rna.tf32.f32 %0, %1;\n" : "=r"(r) : "f"(f));
    return r;
}
__device__ __forceinline__ void mma_tf32(float c[4], const uint32_t a[4], const uint32_t b[2]) {
    asm volatile(
        "mma.sync.aligned.m16n8k8.row.col.f32.tf32.tf32.f32 "
        "{%0,%1,%2,%3}, {%4,%5,%6,%7}, {%8,%9}, {%0,%1,%2,%3};\n"
        : "+f"(c[0]), "+f"(c[1]), "+f"(c[2]), "+f"(c[3])
        : "r"(a[0]), "r"(a[1]), "r"(a[2]), "r"(a[3]), "r"(b[0]), "r"(b[1]));
}

__global__ __launch_bounds__(256, 2)
void k_gemm_tf32(const float* __restrict__ B,      // Wq [FD, CC]
                 const float* __restrict__ bias,   // bq [FD]
                 float*       __restrict__ D) {
    __shared__ float As[2][GBM][SPAD];   // 64 x 20
    __shared__ float Bs[2][GBN][SPAD];   // 128 x 20

    const int tid  = threadIdx.x;
    const int bn   = blockIdx.x;         // 0..3
    const int bm   = blockIdx.y;         // 0..175
    const int warp = tid >> 5;
    const int lane = tid & 31;
    const int wm   = warp >> 2;          // 0..1
    const int wn   = warp & 3;           // 0..3
    const int g    = lane >> 2;          // 0..7
    const int t    = lane & 3;           // 0..3

    // stage loader mapping: 4 threads per row, one float4 each
    const int lrow = tid >> 2;           // 0..63
    const int lc4  = (tid & 3) << 2;     // 0,4,8,12
    const float* Ab  = g_Ag + (size_t)(bm * GBM + lrow) * CC + lc4;
    const float* Bb0 = B    + (size_t)(bn * GBN + lrow) * CC + lc4;
    const float* Bb1 = B    + (size_t)(bn * GBN + lrow + 64) * CC + lc4;

    float acc[2][4][4];
#pragma unroll
    for (int mi = 0; mi < 2; mi++)
#pragma unroll
        for (int ni = 0; ni < 4; ni++)
#pragma unroll
            for (int r = 0; r < 4; r++) acc[mi][ni][r] = 0.f;

    // prologue: stage 0
    cpasync16(&As[0][lrow][lc4],      Ab);
    cpasync16(&Bs[0][lrow][lc4],      Bb0);
    cpasync16(&Bs[0][lrow + 64][lc4], Bb1);
    cpasync_commit();

#pragma unroll 1
    for (int s = 0; s < NSTAGE; ++s) {
        const int buf = s & 1;
        if (s + 1 < NSTAGE) {
            const int k0 = (s + 1) * GBK;
            cpasync16(&As[buf ^ 1][lrow][lc4],      Ab + k0);
            cpasync16(&Bs[buf ^ 1][lrow][lc4],      Bb0 + k0);
            cpasync16(&Bs[buf ^ 1][lrow + 64][lc4], Bb1 + k0);
            cpasync_commit();
            cpasync_wait<1>();
        } else {
            cpasync_wait<0>();
        }
        __syncthreads();

#pragma unroll
        for (int kk = 0; kk < 2; ++kk) {
            const int kb = kk * 8;
            uint32_t a[2][4], bf[4][2];
#pragma unroll
            for (int mi = 0; mi < 2; mi++) {
                const float* p0 = &As[buf][wm * 32 + mi * 16 + g][kb + t];
                const float* p1 = &As[buf][wm * 32 + mi * 16 + g + 8][kb + t];
                a[mi][0] = f2tf(p0[0]);
                a[mi][1] = f2tf(p1[0]);
                a[mi][2] = f2tf(p0[4]);
                a[mi][3] = f2tf(p1[4]);
            }
#pragma unroll
            for (int ni = 0; ni < 4; ni++) {
                const float* p = &Bs[buf][wn * 32 + ni * 8 + g][kb + t];
                bf[ni][0] = f2tf(p[0]);
                bf[ni][1] = f2tf(p[4]);
            }
#pragma unroll
            for (int mi = 0; mi < 2; mi++)
#pragma unroll
                for (int ni = 0; ni < 4; ni++)
                    mma_tf32(acc[mi][ni], a[mi], bf[ni]);
        }
        __syncthreads();   // protect buf before it is refilled at stage s+2
    }

    // epilogue: += bias, store as float2 pairs
#pragma unroll
    for (int ni = 0; ni < 4; ni++) {
        const int c0 = bn * GBN + wn * 32 + ni * 8 + 2 * t;
        const float b0 = __ldg(&bias[c0]);
        const float b1 = __ldg(&bias[c0 + 1]);
#pragma unroll
        for (int mi = 0; mi < 2; mi++) {
            const int r0 = bm * GBM + wm * 32 + mi * 16 + g;
            float2 v0 = make_float2(acc[mi][ni][0] + b0, acc[mi][ni][1] + b1);
            float2 v1 = make_float2(acc[mi][ni][2] + b0, acc[mi][ni][3] + b1);
            *(float2*)(D + (size_t)r0 * FD + c0)       = v0;
            *(float2*)(D + (size_t)(r0 + 8) * FD + c0) = v1;
        }
    }
}

// ---------------------------------------------------------------------------
// launch
// ---------------------------------------------------------------------------
extern "C" void kernel_launch(void* const* d_in, const int* in_sizes, int n_in,
                              void* d_out, int out_size) {
    (void)in_sizes; (void)n_in; (void)out_size;
    const float* inputs     = (const float*)d_in[0];
    const int*   seq_len    = (const int*)  d_in[1];
    const int*   pack_idx   = (const int*)  d_in[2];
    const int*   masked_idx = (const int*)  d_in[3];
    const int*   neg_idx    = (const int*)  d_in[4];
    const float* mask_emb   = (const float*)d_in[5];
    const float* Wq         = (const float*)d_in[6];
    const float* bq         = (const float*)d_in[7];
    float* out = (float*)d_out;

    // regions 1+2 first: gather pre-mask rows, then tensor-core GEMM + bias
    k_gather<<<MTOT, CC>>>(inputs, pack_idx, masked_idx, neg_idx);
    dim3 grid(FD / GBN, MTOT / GBM);   // (4, 176)
    k_gemm_tf32<<<grid, 256>>>(Wq, bq, out + OUT_REGION0);

    // region 0: padded masked copy, then mask-embedding scatter
    k_copy<<<(NB * CC * WW / 4) / 256, 256>>>(inputs, seq_len, out);
    k_mask<<<M1, CC>>>(pack_idx, masked_idx, mask_emb, out);
}

// round 12
// speedup vs baseline: 1.7502x; 1.2895x over previous
#include <cuda_runtime.h>
#include <cstdint>

// ---------------- problem constants (fixed by reference) ----------------
#define NB    16          // batch lines
#define CC    512         // channels (= GEMM K)
#define WW    4096        // max width
#define FD    512         // final dim (= GEMM N)
#define MW    4           // mask width
#define NM    256         // num masks
#define NNEG  10          // num negatives
#define M1    (NM * MW)         // 1024 masked rows
#define M2    (NNEG * NM * MW)  // 10240 negative rows
#define MTOT  (M1 + M2)         // 11264 GEMM rows
#define OUT_REGION0 (NB * CC * WW)   // 33,554,432 floats

// 23 MB scratch: gathered packed rows [MTOT, CC], row-major (K-contiguous)
__device__ float g_Ag[(size_t)MTOT * CC];

// ---------------------------------------------------------------------------
// K1: out[n,c,0,w] = inputs[n,c,0,w] if w < seq_len[n] else 0   (float4 wide)
// ---------------------------------------------------------------------------
__global__ void k_copy(const float* __restrict__ in,
                       const int*   __restrict__ seq_len,
                       float*       __restrict__ out) {
    int idx = blockIdx.x * blockDim.x + threadIdx.x;   // NB*CC*WW/4 lanes
    int w   = (idx & (WW / 4 - 1)) << 2;
    int nc  = idx >> 10;
    int n   = nc >> 9;
    int len = __ldg(&seq_len[n]);
    float4 v = ((const float4*)in)[idx];
    if (w + 3 >= len) {
        if (w + 0 >= len) v.x = 0.f;
        if (w + 1 >= len) v.y = 0.f;
        if (w + 2 >= len) v.z = 0.f;
        v.w = 0.f;
    }
    ((float4*)out)[idx] = v;
}

// ---------------------------------------------------------------------------
// K2: overwrite the 1024 masked positions with tiled mask_emb rows.
// ---------------------------------------------------------------------------
__global__ void k_mask(const int*   __restrict__ pack_idx,
                       const int*   __restrict__ masked_idx,
                       const float* __restrict__ mask_emb,
                       float*       __restrict__ out) {
    int i = blockIdx.x;          // 0..M1-1
    int c = threadIdx.x;         // 0..CC-1
    int f = __ldg(&pack_idx[__ldg(&masked_idx[i])]);
    int n = f >> 12;
    int w = f & (WW - 1);
    out[(n * CC + c) * WW + w] = __ldg(&mask_emb[(i & (MW - 1)) * CC + c]);
}

// ---------------------------------------------------------------------------
// K3: gather the 11264 packed rows (pre-mask values) into contiguous g_Ag.
// ---------------------------------------------------------------------------
__global__ void k_gather(const float* __restrict__ in,
                         const int*   __restrict__ pack_idx,
                         const int*   __restrict__ masked_idx,
                         const int*   __restrict__ neg_idx) {
    int r = blockIdx.x;          // 0..MTOT-1
    int c = threadIdx.x;         // 0..CC-1
    int p = (r < M1) ? __ldg(&masked_idx[r]) : __ldg(&neg_idx[r - M1]);
    int f = __ldg(&pack_idx[p]);
    int n = f >> 12;
    int w = f & (WW - 1);
    g_Ag[r * CC + c] = __ldg(&in[(n * CC + c) * WW + w]);
}

// ---------------------------------------------------------------------------
// K4: D[MTOT, FD] = g_Ag @ Wq^T + bq   via tensor cores (tf32 mma.sync)
//
//   Block tile 64(M) x 128(N), BK=16, 256 threads = 8 warps (2 M x 4 N),
//   warp tile 32x32 -> 2x4 m16n8k8 fragments, fp32 accumulate.
//   Double-buffered smem fed by cp.async; smem rows padded 16->20 floats so
//   fragment LDS is conflict-free (bank = (20g + t) mod 32, all-distinct).
// ---------------------------------------------------------------------------
#define GBM 64
#define GBN 128
#define GBK 16
#define SPAD 20
#define NSTAGE (CC / GBK)     // 32

__device__ __forceinline__ void cpasync16(void* smem_dst, const void* gsrc) {
    unsigned s = (unsigned)__cvta_generic_to_shared(smem_dst);
    asm volatile("cp.async.cg.shared.global [%0], [%1], 16;\n" :: "r"(s), "l"(gsrc));
}
__device__ __forceinline__ void cpasync_commit() {
    asm volatile("cp.async.commit_group;\n" ::: "memory");
}
template<int N> __device__ __forceinline__ void cpasync_wait() {
    asm volatile("cp.async.wait_group %0;\n" :: "n"(N) : "memory");
}
__device__ __forceinline__ uint32_t f2tf(float f) {
    uint32_t r;
    asm("cvt.rna.tf32.f32 %0, %1;\n" : "=r"(r) : "f"(f));
    return r;
}
__device__ __forceinline__ void mma_tf32(float c[4], const uint32_t a[4], const uint32_t b[2]) {
    asm volatile(
        "mma.sync.aligned.m16n8k8.row.col.f32.tf32.tf32.f32 "
        "{%0,%1,%2,%3}, {%4,%5,%6,%7}, {%8,%9}, {%0,%1,%2,%3};\n"
        : "+f"(c[0]), "+f"(c[1]), "+f"(c[2]), "+f"(c[3])
        : "r"(a[0]), "r"(a[1]), "r"(a[2]), "r"(a[3]), "r"(b[0]), "r"(b[1]));
}

__global__ __launch_bounds__(256, 2)
void k_gemm_tf32(const float* __restrict__ B,      // Wq [FD, CC]
                 const float* __restrict__ bias,   // bq [FD]
                 float*       __restrict__ D) {
    __shared__ float As[2][GBM][SPAD];   // 64 x 20
    __shared__ float Bs[2][GBN][SPAD];   // 128 x 20

    const int tid  = threadIdx.x;
    const int bn   = blockIdx.x;         // 0..3
    const int bm   = blockIdx.y;         // 0..175
    const int warp = tid >> 5;
    const int lane = tid & 31;
    const int wm   = warp >> 2;          // 0..1
    const int wn   = warp & 3;           // 0..3
    const int g    = lane >> 2;          // 0..7
    const int t    = lane & 3;           // 0..3

    // stage loader mapping: 4 threads per row, one float4 each
    const int lrow = tid >> 2;           // 0..63
    const int lc4  = (tid & 3) << 2;     // 0,4,8,12
    const float* Ab  = g_Ag + (size_t)(bm * GBM + lrow) * CC + lc4;
    const float* Bb0 = B    + (size_t)(bn * GBN + lrow) * CC + lc4;
    const float* Bb1 = B    + (size_t)(bn * GBN + lrow + 64) * CC + lc4;

    float acc[2][4][4];
#pragma unroll
    for (int mi = 0; mi < 2; mi++)
#pragma unroll
        for (int ni = 0; ni < 4; ni++)
#pragma unroll
            for (int r = 0; r < 4; r++) acc[mi][ni][r] = 0.f;

    // prologue: stage 0
    cpasync16(&As[0][lrow][lc4],      Ab);
    cpasync16(&Bs[0][lrow][lc4],      Bb0);
    cpasync16(&Bs[0][lrow + 64][lc4], Bb1);
    cpasync_commit();

#pragma unroll 1
    for (int s = 0; s < NSTAGE; ++s) {
        const int buf = s & 1;
        if (s + 1 < NSTAGE) {
            const int k0 = (s + 1) * GBK;
            cpasync16(&As[buf ^ 1][lrow][lc4],      Ab + k0);
            cpasync16(&Bs[buf ^ 1][lrow][lc4],      Bb0 + k0);
            cpasync16(&Bs[buf ^ 1][lrow + 64][lc4], Bb1 + k0);
            cpasync_commit();
            cpasync_wait<1>();
        } else {
            cpasync_wait<0>();
        }
        __syncthreads();

#pragma unroll
        for (int kk = 0; kk < 2; ++kk) {
            const int kb = kk * 8;
            uint32_t a[2][4], bf[4][2];
#pragma unroll
            for (int mi = 0; mi < 2; mi++) {
                const float* p0 = &As[buf][wm * 32 + mi * 16 + g][kb + t];
                const float* p1 = &As[buf][wm * 32 + mi * 16 + g + 8][kb + t];
                a[mi][0] = f2tf(p0[0]);
                a[mi][1] = f2tf(p1[0]);
                a[mi][2] = f2tf(p0[4]);
                a[mi][3] = f2tf(p1[4]);
            }
#pragma unroll
            for (int ni = 0; ni < 4; ni++) {
                const float* p = &Bs[buf][wn * 32 + ni * 8 + g][kb + t];
                bf[ni][0] = f2tf(p[0]);
                bf[ni][1] = f2tf(p[4]);
            }
#pragma unroll
            for (int mi = 0; mi < 2; mi++)
#pragma unroll
                for (int ni = 0; ni < 4; ni++)
                    mma_tf32(acc[mi][ni], a[mi], bf[ni]);
        }
        __syncthreads();   // protect buf before it is refilled at stage s+2
    }

    // epilogue: += bias, store as float2 pairs
#pragma unroll
    for (int ni = 0; ni < 4; ni++) {
        const int c0 = bn * GBN + wn * 32 + ni * 8 + 2 * t;
        const float b0 = __ldg(&bias[c0]);
        const float b1 = __ldg(&bias[c0 + 1]);
#pragma unroll
        for (int mi = 0; mi < 2; mi++) {
            const int r0 = bm * GBM + wm * 32 + mi * 16 + g;
            float2 v0 = make_float2(acc[mi][ni][0] + b0, acc[mi][ni][1] + b1);
            float2 v1 = make_float2(acc[mi][ni][2] + b0, acc[mi][ni][3] + b1);
            *(float2*)(D + (size_t)r0 * FD + c0)       = v0;
            *(float2*)(D + (size_t)(r0 + 8) * FD + c0) = v1;
        }
    }
}

// ---------------------------------------------------------------------------
// launch
// ---------------------------------------------------------------------------
extern "C" void kernel_launch(void* const* d_in, const int* in_sizes, int n_in,
                              void* d_out, int out_size) {
    (void)in_sizes; (void)n_in; (void)out_size;
    const float* inputs     = (const float*)d_in[0];
    const int*   seq_len    = (const int*)  d_in[1];
    const int*   pack_idx   = (const int*)  d_in[2];
    const int*   masked_idx = (const int*)  d_in[3];
    const int*   neg_idx    = (const int*)  d_in[4];
    const float* mask_emb   = (const float*)d_in[5];
    const float* Wq         = (const float*)d_in[6];
    const float* bq         = (const float*)d_in[7];
    float* out = (float*)d_out;

    // regions 1+2 first: gather pre-mask rows, then tensor-core GEMM + bias
    k_gather<<<MTOT, CC>>>(inputs, pack_idx, masked_idx, neg_idx);
    dim3 grid(FD / GBN, MTOT / GBM);   // (4, 176)
    k_gemm_tf32<<<grid, 256>>>(Wq, bq, out + OUT_REGION0);

    // region 0: padded masked copy, then mask-embedding scatter
    k_copy<<<(NB * CC * WW / 4) / 256, 256>>>(inputs, seq_len, out);
    k_mask<<<M1, CC>>>(pack_idx, masked_idx, mask_emb, out);
}